// round 16
// baseline (speedup 1.0000x reference)
#include <cuda_runtime.h>
#include <cuda_fp16.h>
#include <math.h>
#include <stdint.h>

#define T_LEN 16384
#define OBS_D 256
#define MLP_D 1024
#define REC_D 1024
#define G3_D  3072
#define ACT_D 18
#define P3N   24
#define STEPS 26
#define GEMM_STEPS 9
#define TAIL_BLOCKS 128

typedef __half f16;

// ---------------- scratch (device globals; no allocation allowed) ----------------
__device__ __align__(16) f16   g_x2[(size_t)T_LEN * OBS_D];
__device__ __align__(16) f16   g_prew2[(size_t)MLP_D * OBS_D];
__device__ __align__(16) f16   g_feat2[(size_t)T_LEN * MLP_D];
__device__ __align__(16) f16   g_wih2[(size_t)G3_D * MLP_D];
__device__ __align__(16) f16   g_whh2[(size_t)G3_D * REC_D];
__device__ __align__(16) f16   g_p1w2[(size_t)MLP_D * REC_D];
__device__ __align__(16) f16   g_p2w2[(size_t)MLP_D * MLP_D];
__device__ __align__(16) f16   g_p3w2[(size_t)P3N * MLP_D];
__device__ __align__(16) f16   g_states2[(size_t)T_LEN * REC_D];
__device__ __align__(16) f16   g_y12[(size_t)T_LEN * MLP_D];
__device__ __align__(16) f16   g_igates[(size_t)T_LEN * G3_D];
__device__ __align__(16) f16   g_hg[(size_t)T_LEN * G3_D];
__device__ __align__(16) f16   g_y2h[(size_t)T_LEN * MLP_D];
__device__ __align__(16) float g_states[(size_t)T_LEN * REC_D];
__device__ float g_hg0[G3_D];
__device__ int   g_age[T_LEN];
__device__ int   g_perm[T_LEN];
__device__ int   g_counts[STEPS + 1];
__device__ int   g_offsets[STEPS + 1];
__device__ int   g_flags[4];
__device__ unsigned g_bar;

// ---------------- helpers ----------------
__device__ __forceinline__ float sigf(float x) { return 1.0f / (1.0f + expf(-x)); }
__device__ __forceinline__ float mishf(float x) {
    float sp = (x > 15.0f) ? x : log1pf(expf(x));
    return x * tanhf(sp);
}
__device__ __forceinline__ uint32_t smem_u32(const void* p) {
    return (uint32_t)__cvta_generic_to_shared(p);
}
__device__ __forceinline__ uint32_t pack2h(f16 a, f16 b) {
    __half2 t; t.x = a; t.y = b;
    return *(uint32_t*)&t;
}
__device__ __forceinline__ void store_state(int t, int j, float v) {
    g_states[(size_t)t * REC_D + j] = v;
    g_states2[(size_t)t * REC_D + j] = __float2half(v);
}
__device__ __forceinline__ float ldh(const f16* p) { return __half2float(*p); }

// ---------------- async / mma primitives (plain compute_100-legal) ----------------
__device__ __forceinline__ void cpasync16(uint32_t sa, const void* ga) {
    asm volatile("cp.async.cg.shared.global [%0], [%1], 16;" :: "r"(sa), "l"(ga));
}
__device__ __forceinline__ void cp_commit() { asm volatile("cp.async.commit_group;" ::: "memory"); }
__device__ __forceinline__ void cp_wait2() { asm volatile("cp.async.wait_group 2;" ::: "memory"); }
__device__ __forceinline__ void cp_wait1() { asm volatile("cp.async.wait_group 1;" ::: "memory"); }
__device__ __forceinline__ void cp_wait0() { asm volatile("cp.async.wait_group 0;" ::: "memory"); }

__device__ __forceinline__ void ldmx4(uint32_t addr, uint32_t& r0, uint32_t& r1, uint32_t& r2, uint32_t& r3) {
    asm volatile("ldmatrix.sync.aligned.m8n8.x4.shared.b16 {%0,%1,%2,%3}, [%4];"
                 : "=r"(r0), "=r"(r1), "=r"(r2), "=r"(r3) : "r"(addr));
}
__device__ __forceinline__ void mma_h(float* c, const uint32_t* a, const uint32_t* b) {
    asm volatile("mma.sync.aligned.m16n8k16.row.col.f32.f16.f16.f32 "
                 "{%0,%1,%2,%3}, {%4,%5,%6,%7}, {%8,%9}, {%0,%1,%2,%3};"
                 : "+f"(c[0]), "+f"(c[1]), "+f"(c[2]), "+f"(c[3])
                 : "r"(a[0]), "r"(a[1]), "r"(a[2]), "r"(a[3]), "r"(b[0]), "r"(b[1]));
}

// ---------------- merged segment analysis (single launch) ----------------
__device__ __forceinline__ bool start_val(const void* p, int mode, int u) {
    if (mode == 0) return ((const unsigned char*)p)[u] != 0;
    if (mode == 1) return ((const int*)p)[u] != 0;
    return ((const float*)p)[u] != 0.0f;
}

__global__ void __launch_bounds__(1024)
analyze_kernel(const unsigned char* __restrict__ p) {
    __shared__ int s_nz[4];
    __shared__ int s_counts[STEPS + 1];
    __shared__ int s_off[STEPS + 1];
    __shared__ int s_cur[STEPS + 1];
    __shared__ int s_mode;
    int tid = threadIdx.x;
    if (tid < 4) s_nz[tid] = 0;
    if (tid < STEPS + 1) { s_counts[tid] = 0; s_cur[tid] = 0; }
    if (tid == 0) g_bar = 0;
    __syncthreads();
    int cnt = 0;
    for (int i = tid; i < T_LEN; i += 1024) cnt += (p[i] != 0);
    atomicAdd(&s_nz[tid & 3], cnt);
    __syncthreads();
    if (tid == 0) {
        int rest = s_nz[1] + s_nz[2] + s_nz[3];
        int mode;
        if (rest > 0) mode = (s_nz[0] == 0) ? 2 : 0;
        else          mode = (s_nz[0] > 0) ? 1 : 0;
        g_flags[0] = mode;
        bool s0;
        if (mode == 0)      s0 = p[0] != 0;
        else if (mode == 1) s0 = ((const int*)p)[0] != 0;
        else                s0 = ((const float*)p)[0] != 0.0f;
        g_flags[1] = s0 ? 1 : 0;
        s_mode = mode;
    }
    __syncthreads();
    int mode = s_mode;
    for (int t = tid; t < T_LEN; t += 1024) {
        int k = 0, tt = t;
        while (tt > 0 && !start_val(p, mode, tt)) { tt--; k++; }
        g_age[t] = k;
        int b = k < STEPS ? k : STEPS;
        atomicAdd(&s_counts[b], 1);
    }
    __syncthreads();
    if (tid == 0) {
        int acc = 0;
        for (int b = 0; b <= STEPS; b++) { s_off[b] = acc; g_offsets[b] = acc; acc += s_counts[b]; }
    }
    if (tid < STEPS + 1) g_counts[tid] = s_counts[tid];
    __syncthreads();
    for (int t = tid; t < T_LEN; t += 1024) {
        int a = g_age[t];
        int b = a < STEPS ? a : STEPS;
        int pos = s_off[b] + atomicAdd(&s_cur[b], 1);
        g_perm[pos] = t;
    }
}

// ---------------- merged fp32->fp16 conversions (one launch) ----------------
__global__ void conv_all(const float* s0, f16* d0, size_t n0,
                         const float* s1, f16* d1, size_t n1,
                         const float* s2, f16* d2, size_t n2,
                         const float* s3, f16* d3, size_t n3,
                         const float* s4, f16* d4, size_t n4,
                         const float* s5, f16* d5, size_t n5,
                         const float* s6, f16* d6) {
    size_t stride = (size_t)gridDim.x * blockDim.x;
    size_t i0 = (size_t)blockIdx.x * blockDim.x + threadIdx.x;
    for (size_t i = i0; i < n0; i += stride) d0[i] = __float2half(s0[i]);
    for (size_t i = i0; i < n1; i += stride) d1[i] = __float2half(s1[i]);
    for (size_t i = i0; i < n2; i += stride) d2[i] = __float2half(s2[i]);
    for (size_t i = i0; i < n3; i += stride) d3[i] = __float2half(s3[i]);
    for (size_t i = i0; i < n4; i += stride) d4[i] = __float2half(s4[i]);
    for (size_t i = i0; i < n5; i += stride) d5[i] = __float2half(s5[i]);
    for (size_t i = i0; i < (size_t)P3N * MLP_D; i += stride) {
        int a = (int)(i >> 10);
        d6[i] = (a < ACT_D) ? __float2half(s6[(size_t)a * MLP_D + (i & 1023)]) : __float2half(0.0f);
    }
}

// ---------------- mma.sync GEMM (128x256, 256 threads, warp 64x64, BK=64, 4 stages) ------
#define STG_A_SZ 16384
#define STG_B_SZ 32768
#define STG_SZ (STG_A_SZ + STG_B_SZ)
#define NSTG 4
#define SMEM_GEMM (NSTG * STG_SZ)

// 64B-row swizzle (4 segs) — used by small-tile + p3 kernels
__device__ __forceinline__ uint32_t swz(uint32_t base, int r, int seg) {
    return base + r * 64 + 16 * (seg ^ ((r >> 1) & 3));
}
// 128B-row swizzle (8 segs, 8-row atom)
__device__ __forceinline__ uint32_t swz128(uint32_t base, int r, int seg) {
    return base + r * 128 + 16 * (seg ^ (r & 7));
}

template <int GATHER>
__device__ __forceinline__ void load_stage(const f16* __restrict__ A, const f16* __restrict__ B,
                                           const int* __restrict__ perm, int M,
                                           int rowBase, int colBase, int K, int chunk,
                                           uint32_t sA, uint32_t sB, int tid) {
    // A: 128 rows x 8 segs = 1024 cp.async (4 per thread)
#pragma unroll
    for (int i = 0; i < 4; i++) {
        int o = tid + i * 256;
        int r = o >> 3, seg = o & 7;
        const f16* src;
        if (GATHER) {
            int gi = rowBase + r;
            gi = gi < M - 1 ? gi : M - 1;
            int t = __ldg(&perm[gi]);
            src = A + (size_t)(t - 1) * K + chunk * 64 + (size_t)seg * 8;
        } else {
            src = A + (size_t)(rowBase + r) * K + chunk * 64 + (size_t)seg * 8;
        }
        cpasync16(swz128(sA, r, seg), src);
    }
    // B: 256 rows x 8 segs = 2048 cp.async (8 per thread)
    const f16* Bb = B + (size_t)colBase * K + chunk * 64;
#pragma unroll
    for (int i = 0; i < 8; i++) {
        int o = tid + i * 256;
        int r = o >> 3, seg = o & 7;
        cpasync16(swz128(sB, r, seg), Bb + (size_t)r * K + seg * 8);
    }
}

template <int MISH, int HALFOUT, int GATHER>
__global__ void __launch_bounds__(256)
gemm_ca(const f16* __restrict__ A, const f16* __restrict__ B,
        const float* __restrict__ bias, float* __restrict__ Cf, f16* __restrict__ Cs,
        int Ntot, int K, const int* __restrict__ Mptr, int Mfix, int bucketK) {
    extern __shared__ __align__(16) char dsm[];
    int tid = threadIdx.x, wid = tid >> 5, lane = tid & 31;
    int wm = wid >> 2, wn = wid & 3;   // 2 x 4 warps, warp tile 64x64
    int M = Mptr ? *Mptr : Mfix;
    const int* perm = GATHER ? (g_perm + g_offsets[bucketK]) : (const int*)0;
    int colBase = blockIdx.x * 256;
    int NC = K >> 6;
    uint32_t sbase = smem_u32(dsm);

    for (int mtile = blockIdx.y; mtile * 128 < M; mtile += gridDim.y) {
        int rowBase = mtile * 128;
        float acc[4][8][4];
#pragma unroll
        for (int mt = 0; mt < 4; mt++)
#pragma unroll
            for (int nt = 0; nt < 8; nt++)
#pragma unroll
                for (int q = 0; q < 4; q++) acc[mt][nt][q] = 0.0f;

#pragma unroll
        for (int p = 0; p < 3; p++) {
            uint32_t sg = sbase + p * STG_SZ;
            load_stage<GATHER>(A, B, perm, M, rowBase, colBase, K, p, sg, sg + STG_A_SZ, tid);
            cp_commit();
        }

        for (int c = 0; c < NC; c++) {
            cp_wait2();
            __syncthreads();
            if (c + 3 < NC) {
                int s = (c + 3) & 3;
                uint32_t sg = sbase + s * STG_SZ;
                load_stage<GATHER>(A, B, perm, M, rowBase, colBase, K, c + 3, sg, sg + STG_A_SZ, tid);
            }
            cp_commit();

            uint32_t sA = sbase + (c & 3) * STG_SZ;
            uint32_t sB = sA + STG_A_SZ;
#pragma unroll
            for (int kk2 = 0; kk2 < 4; kk2++) {
                int seg = kk2 * 2 + (lane >> 4);
                uint32_t af[4][4];
#pragma unroll
                for (int mt = 0; mt < 4; mt++) {
                    int r = wm * 64 + mt * 16 + (lane & 15);
                    ldmx4(swz128(sA, r, seg), af[mt][0], af[mt][1], af[mt][2], af[mt][3]);
                }
                uint32_t bb[8][2];
#pragma unroll
                for (int nb = 0; nb < 4; nb++) {
                    int r = wn * 64 + nb * 16 + (lane & 15);
                    uint32_t r0, r1, r2, r3;
                    ldmx4(swz128(sB, r, seg), r0, r1, r2, r3);
                    bb[2 * nb][0] = r0;     bb[2 * nb][1] = r2;
                    bb[2 * nb + 1][0] = r1; bb[2 * nb + 1][1] = r3;
                }
#pragma unroll
                for (int mt = 0; mt < 4; mt++)
#pragma unroll
                    for (int nt = 0; nt < 8; nt++)
                        mma_h(acc[mt][nt], af[mt], bb[nt]);
            }
        }
        cp_wait0();
        __syncthreads();

        int rg = lane >> 2, cg = (lane & 3) * 2;
#pragma unroll
        for (int mt = 0; mt < 4; mt++) {
            int R0 = rowBase + wm * 64 + mt * 16 + rg;
#pragma unroll
            for (int nt = 0; nt < 8; nt++) {
                int C = colBase + wn * 64 + nt * 8 + cg;
                float b0 = bias ? bias[C] : 0.0f;
                float b1 = bias ? bias[C + 1] : 0.0f;
                float v00 = acc[mt][nt][0] + b0, v01 = acc[mt][nt][1] + b1;
                float v10 = acc[mt][nt][2] + b0, v11 = acc[mt][nt][3] + b1;
                if (MISH) { v00 = mishf(v00); v01 = mishf(v01); v10 = mishf(v10); v11 = mishf(v11); }
                if (HALFOUT) {
                    *(uint32_t*)&Cs[(size_t)R0 * Ntot + C] =
                        pack2h(__float2half(v00), __float2half(v01));
                    *(uint32_t*)&Cs[(size_t)(R0 + 8) * Ntot + C] =
                        pack2h(__float2half(v10), __float2half(v11));
                } else {
                    float2 a; a.x = v00; a.y = v01;
                    float2 b; b.x = v10; b.y = v11;
                    *(float2*)&Cf[(size_t)R0 * Ntot + C] = a;
                    *(float2*)&Cf[(size_t)(R0 + 8) * Ntot + C] = b;
                }
            }
        }
    }
}

// ---------------- small-tile GEMM (64x128) for small GRU steps ----------------
#define SSTG_A_SZ 4096
#define SSTG_B_SZ 8192
#define SSTG_SZ (SSTG_A_SZ + SSTG_B_SZ)
#define SMEM_SGEMM (4 * SSTG_SZ)

__device__ __forceinline__ void load_stage_sm(const f16* __restrict__ A, const f16* __restrict__ B,
                                              const int* __restrict__ perm, int M,
                                              int rowBase, int colBase, int K, int chunk,
                                              uint32_t sA, uint32_t sB, int tid) {
    {
        int r = tid >> 2, seg = tid & 3;
        int gi = rowBase + r;
        gi = gi < M - 1 ? gi : M - 1;
        int t = __ldg(&perm[gi]);
        cpasync16(swz(sA, r, seg), A + (size_t)(t - 1) * K + chunk * 32 + (size_t)seg * 8);
    }
    const f16* Bb = B + (size_t)colBase * K + chunk * 32;
#pragma unroll
    for (int i = 0; i < 2; i++) {
        int o = tid + i * 256;
        int r = o >> 2, seg = o & 3;
        cpasync16(swz(sB, r, seg), Bb + (size_t)r * K + seg * 8);
    }
}

__global__ void __launch_bounds__(256)
gemm_sm(const f16* __restrict__ A, const f16* __restrict__ B, f16* __restrict__ Cs,
        int Ntot, int K, const int* __restrict__ Mptr, int bucketK) {
    extern __shared__ __align__(16) char dsm[];
    int tid = threadIdx.x, wid = tid >> 5, lane = tid & 31;
    int wm = wid >> 2, wn = wid & 3;
    int M = *Mptr;
    const int* perm = g_perm + g_offsets[bucketK];
    int colBase = blockIdx.x * 128;
    int NC = K >> 5;
    uint32_t sbase = smem_u32(dsm);

    for (int mtile = blockIdx.y; mtile * 64 < M; mtile += gridDim.y) {
        int rowBase = mtile * 64;
        float acc[2][4][4];
#pragma unroll
        for (int mt = 0; mt < 2; mt++)
#pragma unroll
            for (int nt = 0; nt < 4; nt++)
#pragma unroll
                for (int q = 0; q < 4; q++) acc[mt][nt][q] = 0.0f;

#pragma unroll
        for (int p = 0; p < 3; p++) {
            uint32_t sg = sbase + p * SSTG_SZ;
            load_stage_sm(A, B, perm, M, rowBase, colBase, K, p, sg, sg + SSTG_A_SZ, tid);
            cp_commit();
        }

        for (int c = 0; c < NC; c++) {
            cp_wait2();
            __syncthreads();
            if (c + 3 < NC) {
                int s = (c + 3) & 3;
                uint32_t sg = sbase + s * SSTG_SZ;
                load_stage_sm(A, B, perm, M, rowBase, colBase, K, c + 3, sg, sg + SSTG_A_SZ, tid);
            }
            cp_commit();

            uint32_t sA = sbase + (c & 3) * SSTG_SZ;
            uint32_t sB = sA + SSTG_A_SZ;
#pragma unroll
            for (int kk2 = 0; kk2 < 2; kk2++) {
                int seg = kk2 * 2 + (lane >> 4);
                uint32_t af[2][4];
#pragma unroll
                for (int mt = 0; mt < 2; mt++) {
                    int r = wm * 32 + mt * 16 + (lane & 15);
                    ldmx4(swz(sA, r, seg), af[mt][0], af[mt][1], af[mt][2], af[mt][3]);
                }
                uint32_t bb[4][2];
#pragma unroll
                for (int nb = 0; nb < 2; nb++) {
                    int r = wn * 32 + nb * 16 + (lane & 15);
                    uint32_t r0, r1, r2, r3;
                    ldmx4(swz(sB, r, seg), r0, r1, r2, r3);
                    bb[2 * nb][0] = r0;     bb[2 * nb][1] = r2;
                    bb[2 * nb + 1][0] = r1; bb[2 * nb + 1][1] = r3;
                }
#pragma unroll
                for (int mt = 0; mt < 2; mt++)
#pragma unroll
                    for (int nt = 0; nt < 4; nt++)
                        mma_h(acc[mt][nt], af[mt], bb[nt]);
            }
        }
        cp_wait0();
        __syncthreads();

        int rg = lane >> 2, cg = (lane & 3) * 2;
#pragma unroll
        for (int mt = 0; mt < 2; mt++) {
            int R0 = rowBase + wm * 32 + mt * 16 + rg;
#pragma unroll
            for (int nt = 0; nt < 4; nt++) {
                int C = colBase + wn * 32 + nt * 8 + cg;
                *(uint32_t*)&Cs[(size_t)R0 * Ntot + C] =
                    pack2h(__float2half(acc[mt][nt][0]), __float2half(acc[mt][nt][1]));
                *(uint32_t*)&Cs[(size_t)(R0 + 8) * Ntot + C] =
                    pack2h(__float2half(acc[mt][nt][2]), __float2half(acc[mt][nt][3]));
            }
        }
    }
}

// ---------------- p3 head on tensor cores ----------------
#define P3A_SZ 8192
#define P3_BS_OFF (4 * P3A_SZ)
#define P3_BS_STRIDE 1032
#define SMEM_P3 (P3_BS_OFF + P3N * P3_BS_STRIDE * 2)

__global__ void __launch_bounds__(256)
gemm_p3(const f16* __restrict__ A, const f16* __restrict__ B,
        const float* __restrict__ bias, float* __restrict__ out) {
    extern __shared__ __align__(16) char dsm[];
    f16* Bs = (f16*)(dsm + P3_BS_OFF);
    int tid = threadIdx.x, wid = tid >> 5, lane = tid & 31;
    int rowBase = blockIdx.x * 128;
    uint32_t sbase = smem_u32(dsm);

#pragma unroll
    for (int i = 0; i < 12; i++) {
        int o = tid + i * 256;
        int n = o >> 7, k8 = o & 127;
        *(uint4*)&Bs[n * P3_BS_STRIDE + k8 * 8] = *(const uint4*)&B[(size_t)n * MLP_D + k8 * 8];
    }

#pragma unroll
    for (int p = 0; p < 3; p++) {
        uint32_t sg = sbase + p * P3A_SZ;
        const f16* Ab = A + (size_t)rowBase * MLP_D + p * 32;
#pragma unroll
        for (int i = 0; i < 2; i++) {
            int o = tid + i * 256;
            int r = o >> 2, seg = o & 3;
            cpasync16(swz(sg, r, seg), Ab + (size_t)r * MLP_D + seg * 8);
        }
        cp_commit();
    }

    float acc[3][4];
#pragma unroll
    for (int nt = 0; nt < 3; nt++)
#pragma unroll
        for (int q = 0; q < 4; q++) acc[nt][q] = 0.0f;

    int cf = lane >> 2, k0 = (lane & 3) * 2;
    const int NC = MLP_D / 32;
    for (int c = 0; c < NC; c++) {
        cp_wait2();
        __syncthreads();
        if (c + 3 < NC) {
            uint32_t sg = sbase + ((c + 3) & 3) * P3A_SZ;
            const f16* Ab = A + (size_t)rowBase * MLP_D + (c + 3) * 32;
#pragma unroll
            for (int i = 0; i < 2; i++) {
                int o = tid + i * 256;
                int r = o >> 2, seg = o & 3;
                cpasync16(swz(sg, r, seg), Ab + (size_t)r * MLP_D + seg * 8);
            }
        }
        cp_commit();

        uint32_t sA = sbase + (c & 3) * P3A_SZ;
#pragma unroll
        for (int kk2 = 0; kk2 < 2; kk2++) {
            int seg = kk2 * 2 + (lane >> 4);
            uint32_t af[4];
            int r = wid * 16 + (lane & 15);
            ldmx4(swz(sA, r, seg), af[0], af[1], af[2], af[3]);
            int kbase = c * 32 + kk2 * 16;
#pragma unroll
            for (int nt = 0; nt < 3; nt++) {
                int n = nt * 8 + cf;
                uint32_t bfr[2];
                bfr[0] = *(const uint32_t*)&Bs[n * P3_BS_STRIDE + kbase + k0];
                bfr[1] = *(const uint32_t*)&Bs[n * P3_BS_STRIDE + kbase + k0 + 8];
                mma_h(acc[nt], af, bfr);
            }
        }
    }
    cp_wait0();

    int rg = lane >> 2, cg = (lane & 3) * 2;
#pragma unroll
    for (int nt = 0; nt < 3; nt++) {
        int col = nt * 8 + cg;
        int R0 = rowBase + wid * 16 + rg;
        if (col < ACT_D) {
            float b = bias[col];
            out[(size_t)R0 * ACT_D + col] = acc[nt][0] + b;
            out[(size_t)(R0 + 8) * ACT_D + col] = acc[nt][2] + b;
        }
        if (col + 1 < ACT_D) {
            float b = bias[col + 1];
            out[(size_t)R0 * ACT_D + col + 1] = acc[nt][1] + b;
            out[(size_t)(R0 + 8) * ACT_D + col + 1] = acc[nt][3] + b;
        }
    }
}

// ---------------- GRU step k==0 (h_prev == 0) ----------------
__global__ void step0_kernel(const float* __restrict__ b_n) {
    int count = g_counts[0];
    long total = (long)count * REC_D;
    long stride = (long)gridDim.x * blockDim.x;
    for (long idx = (long)blockIdx.x * blockDim.x + threadIdx.x; idx < total; idx += stride) {
        int i = (int)(idx >> 10);
        int j = (int)(idx & 1023);
        int t = g_perm[i];
        float igr = ldh(&g_igates[(size_t)t * G3_D + j]);
        float igz = ldh(&g_igates[(size_t)t * G3_D + 1024 + j]);
        float ign = ldh(&g_igates[(size_t)t * G3_D + 2048 + j]);
        float r = sigf(igr);
        float z = sigf(igz);
        float n = tanhf(ign + r * b_n[j]);
        store_state(t, j, n - z * n);
    }
}

__global__ void fixA_kernel(const float* __restrict__ w_hh, const float* __restrict__ state) {
    if (g_flags[1]) return;
    int j = blockIdx.x * 8 + (threadIdx.x >> 5);
    int lane = threadIdx.x & 31;
    float acc = 0.0f;
    const float* wr = w_hh + (size_t)j * REC_D;
    for (int k = lane; k < REC_D; k += 32) acc += wr[k] * state[k];
#pragma unroll
    for (int o = 16; o > 0; o >>= 1) acc += __shfl_down_sync(0xffffffffu, acc, o);
    if (lane == 0) g_hg0[j] = acc;
}

__global__ void fixB_kernel(const float* __restrict__ state, const float* __restrict__ b_n) {
    if (g_flags[1]) return;
    int j = threadIdx.x;
    float igr = ldh(&g_igates[j]), igz = ldh(&g_igates[1024 + j]), ign = ldh(&g_igates[2048 + j]);
    float r = sigf(igr + g_hg0[j]);
    float z = sigf(igz + g_hg0[1024 + j]);
    float n = tanhf(ign + r * (g_hg0[2048 + j] + b_n[j]));
    float hp = state[j];
    store_state(0, j, n + z * (hp - n));
}

__global__ void gru_gate(const float* __restrict__ b_n, int k) {
    int count = g_counts[k];
    int base = g_offsets[k];
    long total = (long)count * REC_D;
    long stride = (long)gridDim.x * blockDim.x;
    for (long idx = (long)blockIdx.x * blockDim.x + threadIdx.x; idx < total; idx += stride) {
        int i = (int)(idx >> 10);
        int j = (int)(idx & 1023);
        int t = g_perm[base + i];
        float hr = ldh(&g_hg[(size_t)i * G3_D + j]);
        float hz = ldh(&g_hg[(size_t)i * G3_D + 1024 + j]);
        float hn = ldh(&g_hg[(size_t)i * G3_D + 2048 + j]);
        float igr = ldh(&g_igates[(size_t)t * G3_D + j]);
        float igz = ldh(&g_igates[(size_t)t * G3_D + 1024 + j]);
        float ign = ldh(&g_igates[(size_t)t * G3_D + 2048 + j]);
        float hp = g_states[(size_t)(t - 1) * REC_D + j];
        float r = sigf(igr + hr);
        float z = sigf(igz + hz);
        float n = tanhf(ign + r * (hn + b_n[j]));
        store_state(t, j, n + z * (hp - n));
    }
}

// ---------------- persistent tail ----------------
__device__ __forceinline__ void tail_prefetch(int t, __half2* buf, int tid) {
    if (tid < 128) {
        const char* src = (const char*)(g_states2 + (size_t)(t - 1) * REC_D) + tid * 16;
        cpasync16(smem_u32((char*)buf + tid * 16), src);
    }
}

__global__ void __launch_bounds__(256)
gru_tail_persistent(const float* __restrict__ b_n) {
    __shared__ __align__(16) __half2 sh[2][REC_D / 2];
    int tid = threadIdx.x;
    int wid = tid >> 5;
    int j = blockIdx.x * 8 + wid;
    int lane = tid & 31;
    const __half2* wr2 = (const __half2*)(g_whh2 + (size_t)j * REC_D);
    const __half2* wz2 = (const __half2*)(g_whh2 + (size_t)(1024 + j) * REC_D);
    const __half2* wn2 = (const __half2*)(g_whh2 + (size_t)(2048 + j) * REC_D);
    __half2 wr[16], wz[16], wn[16];
#pragma unroll
    for (int q = 0; q < 16; q++) {
        wr[q] = wr2[lane + q * 32];
        wz[q] = wz2[lane + q * 32];
        wn[q] = wn2[lane + q * 32];
    }
    float bn = b_n[j];
    unsigned nb = gridDim.x;
    unsigned bc = 0;

    for (int k = GEMM_STEPS; k < STEPS; k++) {
        int count = g_counts[k];
        int base = g_offsets[k];
        if (count <= 0) continue;
        tail_prefetch(g_perm[base], sh[0], tid);
        cp_commit();
        for (int i = 0; i < count; i++) {
            if (i + 1 < count) tail_prefetch(g_perm[base + i + 1], sh[(i + 1) & 1], tid);
            cp_commit();
            if (i + 1 < count) cp_wait1(); else cp_wait0();
            __syncthreads();
            const __half2* hb = sh[i & 1];
            int t = g_perm[base + i];
            float aR = 0.0f, aZ = 0.0f, aN = 0.0f;
#pragma unroll
            for (int q = 0; q < 16; q++) {
                float2 hf = __half22float2(hb[lane + q * 32]);
                float2 rf = __half22float2(wr[q]);
                float2 zf = __half22float2(wz[q]);
                float2 nf = __half22float2(wn[q]);
                aR += rf.x * hf.x + rf.y * hf.y;
                aZ += zf.x * hf.x + zf.y * hf.y;
                aN += nf.x * hf.x + nf.y * hf.y;
            }
#pragma unroll
            for (int o = 16; o > 0; o >>= 1) {
                aR += __shfl_xor_sync(0xffffffffu, aR, o);
                aZ += __shfl_xor_sync(0xffffffffu, aZ, o);
                aN += __shfl_xor_sync(0xffffffffu, aN, o);
            }
            if (lane == 0) {
                float igr = ldh(&g_igates[(size_t)t * G3_D + j]);
                float igz = ldh(&g_igates[(size_t)t * G3_D + 1024 + j]);
                float ign = ldh(&g_igates[(size_t)t * G3_D + 2048 + j]);
                float hp = __ldcg(&g_states[(size_t)(t - 1) * REC_D + j]);
                float r = sigf(igr + aR);
                float z = sigf(igz + aZ);
                float n = tanhf(ign + r * (aN + bn));
                store_state(t, j, n + z * (hp - n));
            }
            __syncthreads();
        }
        bc++;
        __syncthreads();
        if (tid == 0) {
            __threadfence();
            atomicAdd(&g_bar, 1u);
            while (*((volatile unsigned*)&g_bar) < bc * nb) {}
        }
        __syncthreads();
    }
}

// safety net for age >= STEPS
__global__ void __launch_bounds__(1024)
cleanup_kernel(const float* __restrict__ w_hh, const float* __restrict__ b_n) {
    if (g_counts[STEPS] == 0) return;
    __shared__ int s_t;
    __shared__ int s_cur;
    __shared__ float sh[REC_D];
    int tid = threadIdx.x;
    if (tid == 0) s_cur = STEPS;
    __syncthreads();
    while (true) {
        if (tid == 0) {
            s_t = -1;
            for (int u = s_cur; u < T_LEN; ++u)
                if (g_age[u] >= STEPS) { s_t = u; s_cur = u + 1; break; }
        }
        __syncthreads();
        int t = s_t;
        if (t < 0) break;
        sh[tid] = g_states[(size_t)(t - 1) * REC_D + tid];
        __syncthreads();
        float aRv = 0, aZv = 0, aNv = 0;
        const float* wr = w_hh + (size_t)tid * REC_D;
        const float* wz = w_hh + (size_t)(1024 + tid) * REC_D;
        const float* wn = w_hh + (size_t)(2048 + tid) * REC_D;
        for (int kk = 0; kk < REC_D; kk++) {
            float h = sh[kk];
            aRv += wr[kk] * h; aZv += wz[kk] * h; aNv += wn[kk] * h;
        }
        float igr = ldh(&g_igates[(size_t)t * G3_D + tid]);
        float igz = ldh(&g_igates[(size_t)t * G3_D + 1024 + tid]);
        float ign = ldh(&g_igates[(size_t)t * G3_D + 2048 + tid]);
        float r = sigf(igr + aRv);
        float z = sigf(igz + aZv);
        float n = tanhf(ign + r * (aNv + b_n[tid]));
        float hp = sh[tid];
        store_state(t, tid, n + z * (hp - n));
        __syncthreads();
    }
}

__global__ void copy_state_kernel(float* __restrict__ out) {
    out[threadIdx.x] = g_states[(size_t)(T_LEN - 1) * REC_D + threadIdx.x];
}

// ---------------- host ----------------
extern "C" void kernel_launch(void* const* d_in, const int* in_sizes, int n_in,
                              void* d_out, int out_size) {
    const float* x     = (const float*)d_in[0];
    const float* state = (const float*)d_in[1];
    const void*  start = d_in[2];
    const float* pre_w = (const float*)d_in[4];
    const float* pre_b = (const float*)d_in[5];
    const float* w_ih  = (const float*)d_in[6];
    const float* w_hh  = (const float*)d_in[7];
    const float* b_ih  = (const float*)d_in[8];
    const float* b_n   = (const float*)d_in[9];
    const float* p1_w  = (const float*)d_in[10];
    const float* p1_b  = (const float*)d_in[11];
    const float* p2_w  = (const float*)d_in[12];
    const float* p2_b  = (const float*)d_in[13];
    const float* p3_w  = (const float*)d_in[14];
    const float* p3_b  = (const float*)d_in[15];
    float* out = (float*)d_out;

    f16 *x2, *prew2, *feat2, *wih2, *whh2, *p1w2, *p2w2, *p3w2, *states2, *y12;
    f16 *igates, *hg, *y2h;
    int* counts_dev;
    cudaGetSymbolAddress((void**)&igates, g_igates);
    cudaGetSymbolAddress((void**)&hg, g_hg);
    cudaGetSymbolAddress((void**)&y2h, g_y2h);
    cudaGetSymbolAddress((void**)&x2, g_x2);
    cudaGetSymbolAddress((void**)&prew2, g_prew2);
    cudaGetSymbolAddress((void**)&feat2, g_feat2);
    cudaGetSymbolAddress((void**)&wih2, g_wih2);
    cudaGetSymbolAddress((void**)&whh2, g_whh2);
    cudaGetSymbolAddress((void**)&p1w2, g_p1w2);
    cudaGetSymbolAddress((void**)&p2w2, g_p2w2);
    cudaGetSymbolAddress((void**)&p3w2, g_p3w2);
    cudaGetSymbolAddress((void**)&states2, g_states2);
    cudaGetSymbolAddress((void**)&y12, g_y12);
    cudaGetSymbolAddress((void**)&counts_dev, g_counts);

    cudaFuncSetAttribute(gemm_ca<1, 1, 0>, cudaFuncAttributeMaxDynamicSharedMemorySize, SMEM_GEMM);
    cudaFuncSetAttribute(gemm_ca<0, 1, 0>, cudaFuncAttributeMaxDynamicSharedMemorySize, SMEM_GEMM);
    cudaFuncSetAttribute(gemm_ca<0, 1, 1>, cudaFuncAttributeMaxDynamicSharedMemorySize, SMEM_GEMM);
    cudaFuncSetAttribute(gemm_sm, cudaFuncAttributeMaxDynamicSharedMemorySize, SMEM_SGEMM);
    cudaFuncSetAttribute(gemm_p3, cudaFuncAttributeMaxDynamicSharedMemorySize, SMEM_P3);

    // segment analysis (single launch)
    analyze_kernel<<<1, 1024>>>((const unsigned char*)start);

    // all conversions in one launch
    conv_all<<<1024, 256>>>(pre_w, prew2, (size_t)MLP_D * OBS_D,
                            w_ih, wih2, (size_t)G3_D * MLP_D,
                            w_hh, whh2, (size_t)G3_D * REC_D,
                            p1_w, p1w2, (size_t)MLP_D * REC_D,
                            p2_w, p2w2, (size_t)MLP_D * MLP_D,
                            x, x2, (size_t)T_LEN * OBS_D,
                            p3_w, p3w2);

    // feat = mish(x @ pre_w^T + pre_b)
    gemm_ca<1, 1, 0><<<dim3(MLP_D / 256, 128), 256, SMEM_GEMM>>>(
        x2, prew2, pre_b, nullptr, feat2, MLP_D, OBS_D, nullptr, T_LEN, 0);
    // igates = feat @ w_ih^T + b_ih (fp16 out)
    gemm_ca<0, 1, 0><<<dim3(G3_D / 256, 128), 256, SMEM_GEMM>>>(
        feat2, wih2, b_ih, nullptr, igates, G3_D, MLP_D, nullptr, T_LEN, 0);

    // segment-parallel GRU scan
    step0_kernel<<<2048, 256>>>(b_n);
    fixA_kernel<<<384, 256>>>(w_hh, state);
    fixB_kernel<<<1, 1024>>>(state, b_n);
    for (int k = 1; k < GEMM_STEPS; k++) {
        int est = T_LEN >> k;
        if (k == 1) {
            int gy = est / 128; if (gy < 1) gy = 1; if (gy > 64) gy = 64;
            gemm_ca<0, 1, 1><<<dim3(G3_D / 256, gy), 256, SMEM_GEMM>>>(
                states2, whh2, nullptr, nullptr, hg, G3_D, REC_D, counts_dev + k, 0, k);
        } else {
            int gy = est / 64; if (gy < 1) gy = 1; if (gy > 32) gy = 32;
            gemm_sm<<<dim3(G3_D / 128, gy), 256, SMEM_SGEMM>>>(
                states2, whh2, hg, G3_D, REC_D, counts_dev + k, k);
        }
        gru_gate<<<2048, 256>>>(b_n, k);
    }
    gru_tail_persistent<<<TAIL_BLOCKS, 256>>>(b_n);
    cleanup_kernel<<<1, 1024>>>(w_hh, b_n);

    // post MLP
    gemm_ca<1, 1, 0><<<dim3(MLP_D / 256, 128), 256, SMEM_GEMM>>>(
        states2, p1w2, p1_b, nullptr, y12, MLP_D, REC_D, nullptr, T_LEN, 0);
    gemm_ca<1, 1, 0><<<dim3(MLP_D / 256, 128), 256, SMEM_GEMM>>>(
        y12, p2w2, p2_b, nullptr, y2h, MLP_D, MLP_D, nullptr, T_LEN, 0);
    gemm_p3<<<T_LEN / 128, 256, SMEM_P3>>>(y2h, p3w2, p3_b, out);

    if (out_size >= T_LEN * ACT_D + REC_D)
        copy_state_kernel<<<1, 1024>>>(out + (size_t)T_LEN * ACT_D);
}

// round 17
// speedup vs baseline: 1.2391x; 1.2391x over previous
#include <cuda_runtime.h>
#include <cuda_fp16.h>
#include <math.h>
#include <stdint.h>

#define T_LEN 16384
#define OBS_D 256
#define MLP_D 1024
#define REC_D 1024
#define G3_D  3072
#define ACT_D 18
#define P3N   24
#define STEPS 26
#define GEMM_STEPS 9
#define TAIL_BLOCKS 128

typedef __half f16;

// ---------------- scratch (device globals; no allocation allowed) ----------------
__device__ __align__(16) f16   g_x2[(size_t)T_LEN * OBS_D];
__device__ __align__(16) f16   g_prew2[(size_t)MLP_D * OBS_D];
__device__ __align__(16) f16   g_feat2[(size_t)T_LEN * MLP_D];
__device__ __align__(16) f16   g_wih2[(size_t)G3_D * MLP_D];
__device__ __align__(16) f16   g_whh2[(size_t)G3_D * REC_D];
__device__ __align__(16) f16   g_p1w2[(size_t)MLP_D * REC_D];
__device__ __align__(16) f16   g_p2w2[(size_t)MLP_D * MLP_D];
__device__ __align__(16) f16   g_p3w2[(size_t)P3N * MLP_D];
__device__ __align__(16) f16   g_states2[(size_t)T_LEN * REC_D];
__device__ __align__(16) f16   g_y12[(size_t)T_LEN * MLP_D];
__device__ __align__(16) f16   g_igates[(size_t)T_LEN * G3_D];
__device__ __align__(16) f16   g_hg[(size_t)T_LEN * G3_D];
__device__ __align__(16) f16   g_y2h[(size_t)T_LEN * MLP_D];
__device__ __align__(16) float g_states[(size_t)T_LEN * REC_D];
__device__ float g_hg0[G3_D];
__device__ int   g_age[T_LEN];
__device__ int   g_perm[T_LEN];
__device__ int   g_counts[STEPS + 1];
__device__ int   g_offsets[STEPS + 1];
__device__ int   g_flags[4];
__device__ unsigned g_bar;

// ---------------- helpers ----------------
__device__ __forceinline__ float sigf(float x) { return 1.0f / (1.0f + expf(-x)); }
__device__ __forceinline__ float mishf(float x) {
    float sp = (x > 15.0f) ? x : log1pf(expf(x));
    return x * tanhf(sp);
}
__device__ __forceinline__ uint32_t smem_u32(const void* p) {
    return (uint32_t)__cvta_generic_to_shared(p);
}
__device__ __forceinline__ uint32_t pack2h(f16 a, f16 b) {
    __half2 t; t.x = a; t.y = b;
    return *(uint32_t*)&t;
}
__device__ __forceinline__ void store_state(int t, int j, float v) {
    g_states[(size_t)t * REC_D + j] = v;
    g_states2[(size_t)t * REC_D + j] = __float2half(v);
}
__device__ __forceinline__ float ldh(const f16* p) { return __half2float(*p); }

// ---------------- async / mma primitives (plain compute_100-legal) ----------------
__device__ __forceinline__ void cpasync16(uint32_t sa, const void* ga) {
    asm volatile("cp.async.cg.shared.global [%0], [%1], 16;" :: "r"(sa), "l"(ga));
}
__device__ __forceinline__ void cp_commit() { asm volatile("cp.async.commit_group;" ::: "memory"); }
__device__ __forceinline__ void cp_wait2() { asm volatile("cp.async.wait_group 2;" ::: "memory"); }
__device__ __forceinline__ void cp_wait1() { asm volatile("cp.async.wait_group 1;" ::: "memory"); }
__device__ __forceinline__ void cp_wait0() { asm volatile("cp.async.wait_group 0;" ::: "memory"); }

__device__ __forceinline__ void ldmx4(uint32_t addr, uint32_t& r0, uint32_t& r1, uint32_t& r2, uint32_t& r3) {
    asm volatile("ldmatrix.sync.aligned.m8n8.x4.shared.b16 {%0,%1,%2,%3}, [%4];"
                 : "=r"(r0), "=r"(r1), "=r"(r2), "=r"(r3) : "r"(addr));
}
__device__ __forceinline__ void mma_h(float* c, const uint32_t* a, const uint32_t* b) {
    asm volatile("mma.sync.aligned.m16n8k16.row.col.f32.f16.f16.f32 "
                 "{%0,%1,%2,%3}, {%4,%5,%6,%7}, {%8,%9}, {%0,%1,%2,%3};"
                 : "+f"(c[0]), "+f"(c[1]), "+f"(c[2]), "+f"(c[3])
                 : "r"(a[0]), "r"(a[1]), "r"(a[2]), "r"(a[3]), "r"(b[0]), "r"(b[1]));
}

// ---------------- merged segment analysis (single launch) ----------------
__device__ __forceinline__ bool start_val(const void* p, int mode, int u) {
    if (mode == 0) return ((const unsigned char*)p)[u] != 0;
    if (mode == 1) return ((const int*)p)[u] != 0;
    return ((const float*)p)[u] != 0.0f;
}

__global__ void __launch_bounds__(1024)
analyze_kernel(const unsigned char* __restrict__ p) {
    __shared__ int s_nz[4];
    __shared__ int s_counts[STEPS + 1];
    __shared__ int s_off[STEPS + 1];
    __shared__ int s_cur[STEPS + 1];
    __shared__ int s_mode;
    int tid = threadIdx.x;
    if (tid < 4) s_nz[tid] = 0;
    if (tid < STEPS + 1) { s_counts[tid] = 0; s_cur[tid] = 0; }
    if (tid == 0) g_bar = 0;
    __syncthreads();
    int cnt = 0;
    for (int i = tid; i < T_LEN; i += 1024) cnt += (p[i] != 0);
    atomicAdd(&s_nz[tid & 3], cnt);
    __syncthreads();
    if (tid == 0) {
        int rest = s_nz[1] + s_nz[2] + s_nz[3];
        int mode;
        if (rest > 0) mode = (s_nz[0] == 0) ? 2 : 0;
        else          mode = (s_nz[0] > 0) ? 1 : 0;
        g_flags[0] = mode;
        bool s0;
        if (mode == 0)      s0 = p[0] != 0;
        else if (mode == 1) s0 = ((const int*)p)[0] != 0;
        else                s0 = ((const float*)p)[0] != 0.0f;
        g_flags[1] = s0 ? 1 : 0;
        s_mode = mode;
    }
    __syncthreads();
    int mode = s_mode;
    for (int t = tid; t < T_LEN; t += 1024) {
        int k = 0, tt = t;
        while (tt > 0 && !start_val(p, mode, tt)) { tt--; k++; }
        g_age[t] = k;
        int b = k < STEPS ? k : STEPS;
        atomicAdd(&s_counts[b], 1);
    }
    __syncthreads();
    if (tid == 0) {
        int acc = 0;
        for (int b = 0; b <= STEPS; b++) { s_off[b] = acc; g_offsets[b] = acc; acc += s_counts[b]; }
    }
    if (tid < STEPS + 1) g_counts[tid] = s_counts[tid];
    __syncthreads();
    for (int t = tid; t < T_LEN; t += 1024) {
        int a = g_age[t];
        int b = a < STEPS ? a : STEPS;
        int pos = s_off[b] + atomicAdd(&s_cur[b], 1);
        g_perm[pos] = t;
    }
}

// ---------------- merged fp32->fp16 conversions (one launch) ----------------
__global__ void conv_all(const float* s0, f16* d0, size_t n0,
                         const float* s1, f16* d1, size_t n1,
                         const float* s2, f16* d2, size_t n2,
                         const float* s3, f16* d3, size_t n3,
                         const float* s4, f16* d4, size_t n4,
                         const float* s5, f16* d5, size_t n5,
                         const float* s6, f16* d6) {
    size_t stride = (size_t)gridDim.x * blockDim.x;
    size_t i0 = (size_t)blockIdx.x * blockDim.x + threadIdx.x;
    for (size_t i = i0; i < n0; i += stride) d0[i] = __float2half(s0[i]);
    for (size_t i = i0; i < n1; i += stride) d1[i] = __float2half(s1[i]);
    for (size_t i = i0; i < n2; i += stride) d2[i] = __float2half(s2[i]);
    for (size_t i = i0; i < n3; i += stride) d3[i] = __float2half(s3[i]);
    for (size_t i = i0; i < n4; i += stride) d4[i] = __float2half(s4[i]);
    for (size_t i = i0; i < n5; i += stride) d5[i] = __float2half(s5[i]);
    for (size_t i = i0; i < (size_t)P3N * MLP_D; i += stride) {
        int a = (int)(i >> 10);
        d6[i] = (a < ACT_D) ? __float2half(s6[(size_t)a * MLP_D + (i & 1023)]) : __float2half(0.0f);
    }
}

// ---------------- mma.sync GEMM (128x128, 256 threads, BK=64, 3 stages, 2 CTAs/SM) -------
#define STG_A_SZ 16384
#define STG_B_SZ 16384
#define STG_SZ (STG_A_SZ + STG_B_SZ)
#define NSTG 3
#define SMEM_GEMM (NSTG * STG_SZ)

// 64B-row swizzle (4 segs) — used by small-tile + p3 kernels
__device__ __forceinline__ uint32_t swz(uint32_t base, int r, int seg) {
    return base + r * 64 + 16 * (seg ^ ((r >> 1) & 3));
}
// 128B-row swizzle (8 segs, 8-row atom)
__device__ __forceinline__ uint32_t swz128(uint32_t base, int r, int seg) {
    return base + r * 128 + 16 * (seg ^ (r & 7));
}

template <int GATHER>
__device__ __forceinline__ void load_stage(const f16* __restrict__ A, const f16* __restrict__ B,
                                           const int* __restrict__ perm, int M,
                                           int rowBase, int colBase, int K, int chunk,
                                           uint32_t sA, uint32_t sB, int tid) {
    // A: 128 rows x 8 segs = 1024 cp.async (4 per thread)
#pragma unroll
    for (int i = 0; i < 4; i++) {
        int o = tid + i * 256;
        int r = o >> 3, seg = o & 7;
        const f16* src;
        if (GATHER) {
            int gi = rowBase + r;
            gi = gi < M - 1 ? gi : M - 1;
            int t = __ldg(&perm[gi]);
            src = A + (size_t)(t - 1) * K + chunk * 64 + (size_t)seg * 8;
        } else {
            src = A + (size_t)(rowBase + r) * K + chunk * 64 + (size_t)seg * 8;
        }
        cpasync16(swz128(sA, r, seg), src);
    }
    // B: 128 rows x 8 segs = 1024 cp.async (4 per thread)
    const f16* Bb = B + (size_t)colBase * K + chunk * 64;
#pragma unroll
    for (int i = 0; i < 4; i++) {
        int o = tid + i * 256;
        int r = o >> 3, seg = o & 7;
        cpasync16(swz128(sB, r, seg), Bb + (size_t)r * K + seg * 8);
    }
}

template <int MISH, int HALFOUT, int GATHER>
__global__ void __launch_bounds__(256, 2)
gemm_ca(const f16* __restrict__ A, const f16* __restrict__ B,
        const float* __restrict__ bias, float* __restrict__ Cf, f16* __restrict__ Cs,
        int Ntot, int K, const int* __restrict__ Mptr, int Mfix, int bucketK) {
    extern __shared__ __align__(16) char dsm[];
    int tid = threadIdx.x, wid = tid >> 5, lane = tid & 31;
    int wm = wid >> 1, wn = wid & 1;   // 4 x 2 warps, warp tile 32x64
    int M = Mptr ? *Mptr : Mfix;
    const int* perm = GATHER ? (g_perm + g_offsets[bucketK]) : (const int*)0;
    int colBase = blockIdx.x * 128;
    int NC = K >> 6;
    uint32_t sbase = smem_u32(dsm);

    for (int mtile = blockIdx.y; mtile * 128 < M; mtile += gridDim.y) {
        int rowBase = mtile * 128;
        float acc[2][8][4];
#pragma unroll
        for (int mt = 0; mt < 2; mt++)
#pragma unroll
            for (int nt = 0; nt < 8; nt++)
#pragma unroll
                for (int q = 0; q < 4; q++) acc[mt][nt][q] = 0.0f;

#pragma unroll
        for (int p = 0; p < 2; p++) {
            uint32_t sg = sbase + p * STG_SZ;
            load_stage<GATHER>(A, B, perm, M, rowBase, colBase, K, p, sg, sg + STG_A_SZ, tid);
            cp_commit();
        }

        int slot = 0, nslot = 2;
        for (int c = 0; c < NC; c++) {
            cp_wait1();
            __syncthreads();
            if (c + 2 < NC) {
                uint32_t sg = sbase + nslot * STG_SZ;
                load_stage<GATHER>(A, B, perm, M, rowBase, colBase, K, c + 2, sg, sg + STG_A_SZ, tid);
            }
            cp_commit();

            uint32_t sA = sbase + slot * STG_SZ;
            uint32_t sB = sA + STG_A_SZ;
#pragma unroll
            for (int kk2 = 0; kk2 < 4; kk2++) {
                int seg = kk2 * 2 + (lane >> 4);
                uint32_t af[2][4];
#pragma unroll
                for (int mt = 0; mt < 2; mt++) {
                    int r = wm * 32 + mt * 16 + (lane & 15);
                    ldmx4(swz128(sA, r, seg), af[mt][0], af[mt][1], af[mt][2], af[mt][3]);
                }
                uint32_t bb[8][2];
#pragma unroll
                for (int nb = 0; nb < 4; nb++) {
                    int r = wn * 64 + nb * 16 + (lane & 15);
                    uint32_t r0, r1, r2, r3;
                    ldmx4(swz128(sB, r, seg), r0, r1, r2, r3);
                    bb[2 * nb][0] = r0;     bb[2 * nb][1] = r2;
                    bb[2 * nb + 1][0] = r1; bb[2 * nb + 1][1] = r3;
                }
#pragma unroll
                for (int mt = 0; mt < 2; mt++)
#pragma unroll
                    for (int nt = 0; nt < 8; nt++)
                        mma_h(acc[mt][nt], af[mt], bb[nt]);
            }
            slot = slot + 1 == NSTG ? 0 : slot + 1;
            nslot = nslot + 1 == NSTG ? 0 : nslot + 1;
        }
        cp_wait0();
        __syncthreads();

        int rg = lane >> 2, cg = (lane & 3) * 2;
#pragma unroll
        for (int mt = 0; mt < 2; mt++) {
            int R0 = rowBase + wm * 32 + mt * 16 + rg;
#pragma unroll
            for (int nt = 0; nt < 8; nt++) {
                int C = colBase + wn * 64 + nt * 8 + cg;
                float b0 = bias ? bias[C] : 0.0f;
                float b1 = bias ? bias[C + 1] : 0.0f;
                float v00 = acc[mt][nt][0] + b0, v01 = acc[mt][nt][1] + b1;
                float v10 = acc[mt][nt][2] + b0, v11 = acc[mt][nt][3] + b1;
                if (MISH) { v00 = mishf(v00); v01 = mishf(v01); v10 = mishf(v10); v11 = mishf(v11); }
                if (HALFOUT) {
                    *(uint32_t*)&Cs[(size_t)R0 * Ntot + C] =
                        pack2h(__float2half(v00), __float2half(v01));
                    *(uint32_t*)&Cs[(size_t)(R0 + 8) * Ntot + C] =
                        pack2h(__float2half(v10), __float2half(v11));
                } else {
                    float2 a; a.x = v00; a.y = v01;
                    float2 b; b.x = v10; b.y = v11;
                    *(float2*)&Cf[(size_t)R0 * Ntot + C] = a;
                    *(float2*)&Cf[(size_t)(R0 + 8) * Ntot + C] = b;
                }
            }
        }
    }
}

// ---------------- small-tile GEMM (64x128) for small GRU steps ----------------
#define SSTG_A_SZ 4096
#define SSTG_B_SZ 8192
#define SSTG_SZ (SSTG_A_SZ + SSTG_B_SZ)
#define SMEM_SGEMM (4 * SSTG_SZ)

__device__ __forceinline__ void load_stage_sm(const f16* __restrict__ A, const f16* __restrict__ B,
                                              const int* __restrict__ perm, int M,
                                              int rowBase, int colBase, int K, int chunk,
                                              uint32_t sA, uint32_t sB, int tid) {
    {
        int r = tid >> 2, seg = tid & 3;
        int gi = rowBase + r;
        gi = gi < M - 1 ? gi : M - 1;
        int t = __ldg(&perm[gi]);
        cpasync16(swz(sA, r, seg), A + (size_t)(t - 1) * K + chunk * 32 + (size_t)seg * 8);
    }
    const f16* Bb = B + (size_t)colBase * K + chunk * 32;
#pragma unroll
    for (int i = 0; i < 2; i++) {
        int o = tid + i * 256;
        int r = o >> 2, seg = o & 3;
        cpasync16(swz(sB, r, seg), Bb + (size_t)r * K + seg * 8);
    }
}

__global__ void __launch_bounds__(256, 2)
gemm_sm(const f16* __restrict__ A, const f16* __restrict__ B, f16* __restrict__ Cs,
        int Ntot, int K, const int* __restrict__ Mptr, int bucketK) {
    extern __shared__ __align__(16) char dsm[];
    int tid = threadIdx.x, wid = tid >> 5, lane = tid & 31;
    int wm = wid >> 2, wn = wid & 3;
    int M = *Mptr;
    const int* perm = g_perm + g_offsets[bucketK];
    int colBase = blockIdx.x * 128;
    int NC = K >> 5;
    uint32_t sbase = smem_u32(dsm);

    for (int mtile = blockIdx.y; mtile * 64 < M; mtile += gridDim.y) {
        int rowBase = mtile * 64;
        float acc[2][4][4];
#pragma unroll
        for (int mt = 0; mt < 2; mt++)
#pragma unroll
            for (int nt = 0; nt < 4; nt++)
#pragma unroll
                for (int q = 0; q < 4; q++) acc[mt][nt][q] = 0.0f;

#pragma unroll
        for (int p = 0; p < 3; p++) {
            uint32_t sg = sbase + p * SSTG_SZ;
            load_stage_sm(A, B, perm, M, rowBase, colBase, K, p, sg, sg + SSTG_A_SZ, tid);
            cp_commit();
        }

        for (int c = 0; c < NC; c++) {
            cp_wait2();
            __syncthreads();
            if (c + 3 < NC) {
                int s = (c + 3) & 3;
                uint32_t sg = sbase + s * SSTG_SZ;
                load_stage_sm(A, B, perm, M, rowBase, colBase, K, c + 3, sg, sg + SSTG_A_SZ, tid);
            }
            cp_commit();

            uint32_t sA = sbase + (c & 3) * SSTG_SZ;
            uint32_t sB = sA + SSTG_A_SZ;
#pragma unroll
            for (int kk2 = 0; kk2 < 2; kk2++) {
                int seg = kk2 * 2 + (lane >> 4);
                uint32_t af[2][4];
#pragma unroll
                for (int mt = 0; mt < 2; mt++) {
                    int r = wm * 32 + mt * 16 + (lane & 15);
                    ldmx4(swz(sA, r, seg), af[mt][0], af[mt][1], af[mt][2], af[mt][3]);
                }
                uint32_t bb[4][2];
#pragma unroll
                for (int nb = 0; nb < 2; nb++) {
                    int r = wn * 32 + nb * 16 + (lane & 15);
                    uint32_t r0, r1, r2, r3;
                    ldmx4(swz(sB, r, seg), r0, r1, r2, r3);
                    bb[2 * nb][0] = r0;     bb[2 * nb][1] = r2;
                    bb[2 * nb + 1][0] = r1; bb[2 * nb + 1][1] = r3;
                }
#pragma unroll
                for (int mt = 0; mt < 2; mt++)
#pragma unroll
                    for (int nt = 0; nt < 4; nt++)
                        mma_h(acc[mt][nt], af[mt], bb[nt]);
            }
        }
        cp_wait0();
        __syncthreads();

        int rg = lane >> 2, cg = (lane & 3) * 2;
#pragma unroll
        for (int mt = 0; mt < 2; mt++) {
            int R0 = rowBase + wm * 32 + mt * 16 + rg;
#pragma unroll
            for (int nt = 0; nt < 4; nt++) {
                int C = colBase + wn * 32 + nt * 8 + cg;
                *(uint32_t*)&Cs[(size_t)R0 * Ntot + C] =
                    pack2h(__float2half(acc[mt][nt][0]), __float2half(acc[mt][nt][1]));
                *(uint32_t*)&Cs[(size_t)(R0 + 8) * Ntot + C] =
                    pack2h(__float2half(acc[mt][nt][2]), __float2half(acc[mt][nt][3]));
            }
        }
    }
}

// ---------------- p3 head on tensor cores ----------------
#define P3A_SZ 8192
#define P3_BS_OFF (4 * P3A_SZ)
#define P3_BS_STRIDE 1032
#define SMEM_P3 (P3_BS_OFF + P3N * P3_BS_STRIDE * 2)

__global__ void __launch_bounds__(256)
gemm_p3(const f16* __restrict__ A, const f16* __restrict__ B,
        const float* __restrict__ bias, float* __restrict__ out) {
    extern __shared__ __align__(16) char dsm[];
    f16* Bs = (f16*)(dsm + P3_BS_OFF);
    int tid = threadIdx.x, wid = tid >> 5, lane = tid & 31;
    int rowBase = blockIdx.x * 128;
    uint32_t sbase = smem_u32(dsm);

#pragma unroll
    for (int i = 0; i < 12; i++) {
        int o = tid + i * 256;
        int n = o >> 7, k8 = o & 127;
        *(uint4*)&Bs[n * P3_BS_STRIDE + k8 * 8] = *(const uint4*)&B[(size_t)n * MLP_D + k8 * 8];
    }

#pragma unroll
    for (int p = 0; p < 3; p++) {
        uint32_t sg = sbase + p * P3A_SZ;
        const f16* Ab = A + (size_t)rowBase * MLP_D + p * 32;
#pragma unroll
        for (int i = 0; i < 2; i++) {
            int o = tid + i * 256;
            int r = o >> 2, seg = o & 3;
            cpasync16(swz(sg, r, seg), Ab + (size_t)r * MLP_D + seg * 8);
        }
        cp_commit();
    }

    float acc[3][4];
#pragma unroll
    for (int nt = 0; nt < 3; nt++)
#pragma unroll
        for (int q = 0; q < 4; q++) acc[nt][q] = 0.0f;

    int cf = lane >> 2, k0 = (lane & 3) * 2;
    const int NC = MLP_D / 32;
    for (int c = 0; c < NC; c++) {
        cp_wait2();
        __syncthreads();
        if (c + 3 < NC) {
            uint32_t sg = sbase + ((c + 3) & 3) * P3A_SZ;
            const f16* Ab = A + (size_t)rowBase * MLP_D + (c + 3) * 32;
#pragma unroll
            for (int i = 0; i < 2; i++) {
                int o = tid + i * 256;
                int r = o >> 2, seg = o & 3;
                cpasync16(swz(sg, r, seg), Ab + (size_t)r * MLP_D + seg * 8);
            }
        }
        cp_commit();

        uint32_t sA = sbase + (c & 3) * P3A_SZ;
#pragma unroll
        for (int kk2 = 0; kk2 < 2; kk2++) {
            int seg = kk2 * 2 + (lane >> 4);
            uint32_t af[4];
            int r = wid * 16 + (lane & 15);
            ldmx4(swz(sA, r, seg), af[0], af[1], af[2], af[3]);
            int kbase = c * 32 + kk2 * 16;
#pragma unroll
            for (int nt = 0; nt < 3; nt++) {
                int n = nt * 8 + cf;
                uint32_t bfr[2];
                bfr[0] = *(const uint32_t*)&Bs[n * P3_BS_STRIDE + kbase + k0];
                bfr[1] = *(const uint32_t*)&Bs[n * P3_BS_STRIDE + kbase + k0 + 8];
                mma_h(acc[nt], af, bfr);
            }
        }
    }
    cp_wait0();

    int rg = lane >> 2, cg = (lane & 3) * 2;
#pragma unroll
    for (int nt = 0; nt < 3; nt++) {
        int col = nt * 8 + cg;
        int R0 = rowBase + wid * 16 + rg;
        if (col < ACT_D) {
            float b = bias[col];
            out[(size_t)R0 * ACT_D + col] = acc[nt][0] + b;
            out[(size_t)(R0 + 8) * ACT_D + col] = acc[nt][2] + b;
        }
        if (col + 1 < ACT_D) {
            float b = bias[col + 1];
            out[(size_t)R0 * ACT_D + col + 1] = acc[nt][1] + b;
            out[(size_t)(R0 + 8) * ACT_D + col + 1] = acc[nt][3] + b;
        }
    }
}

// ---------------- GRU step k==0 (h_prev == 0) ----------------
__global__ void step0_kernel(const float* __restrict__ b_n) {
    int count = g_counts[0];
    long total = (long)count * REC_D;
    long stride = (long)gridDim.x * blockDim.x;
    for (long idx = (long)blockIdx.x * blockDim.x + threadIdx.x; idx < total; idx += stride) {
        int i = (int)(idx >> 10);
        int j = (int)(idx & 1023);
        int t = g_perm[i];
        float igr = ldh(&g_igates[(size_t)t * G3_D + j]);
        float igz = ldh(&g_igates[(size_t)t * G3_D + 1024 + j]);
        float ign = ldh(&g_igates[(size_t)t * G3_D + 2048 + j]);
        float r = sigf(igr);
        float z = sigf(igz);
        float n = tanhf(ign + r * b_n[j]);
        store_state(t, j, n - z * n);
    }
}

__global__ void fixA_kernel(const float* __restrict__ w_hh, const float* __restrict__ state) {
    if (g_flags[1]) return;
    int j = blockIdx.x * 8 + (threadIdx.x >> 5);
    int lane = threadIdx.x & 31;
    float acc = 0.0f;
    const float* wr = w_hh + (size_t)j * REC_D;
    for (int k = lane; k < REC_D; k += 32) acc += wr[k] * state[k];
#pragma unroll
    for (int o = 16; o > 0; o >>= 1) acc += __shfl_down_sync(0xffffffffu, acc, o);
    if (lane == 0) g_hg0[j] = acc;
}

__global__ void fixB_kernel(const float* __restrict__ state, const float* __restrict__ b_n) {
    if (g_flags[1]) return;
    int j = threadIdx.x;
    float igr = ldh(&g_igates[j]), igz = ldh(&g_igates[1024 + j]), ign = ldh(&g_igates[2048 + j]);
    float r = sigf(igr + g_hg0[j]);
    float z = sigf(igz + g_hg0[1024 + j]);
    float n = tanhf(ign + r * (g_hg0[2048 + j] + b_n[j]));
    float hp = state[j];
    store_state(0, j, n + z * (hp - n));
}

__global__ void gru_gate(const float* __restrict__ b_n, int k) {
    int count = g_counts[k];
    int base = g_offsets[k];
    long total = (long)count * REC_D;
    long stride = (long)gridDim.x * blockDim.x;
    for (long idx = (long)blockIdx.x * blockDim.x + threadIdx.x; idx < total; idx += stride) {
        int i = (int)(idx >> 10);
        int j = (int)(idx & 1023);
        int t = g_perm[base + i];
        float hr = ldh(&g_hg[(size_t)i * G3_D + j]);
        float hz = ldh(&g_hg[(size_t)i * G3_D + 1024 + j]);
        float hn = ldh(&g_hg[(size_t)i * G3_D + 2048 + j]);
        float igr = ldh(&g_igates[(size_t)t * G3_D + j]);
        float igz = ldh(&g_igates[(size_t)t * G3_D + 1024 + j]);
        float ign = ldh(&g_igates[(size_t)t * G3_D + 2048 + j]);
        float hp = g_states[(size_t)(t - 1) * REC_D + j];
        float r = sigf(igr + hr);
        float z = sigf(igz + hz);
        float n = tanhf(ign + r * (hn + b_n[j]));
        store_state(t, j, n + z * (hp - n));
    }
}

// ---------------- persistent tail ----------------
__device__ __forceinline__ void tail_prefetch(int t, __half2* buf, int tid) {
    if (tid < 128) {
        const char* src = (const char*)(g_states2 + (size_t)(t - 1) * REC_D) + tid * 16;
        cpasync16(smem_u32((char*)buf + tid * 16), src);
    }
}

__global__ void __launch_bounds__(256)
gru_tail_persistent(const float* __restrict__ b_n) {
    __shared__ __align__(16) __half2 sh[2][REC_D / 2];
    int tid = threadIdx.x;
    int wid = tid >> 5;
    int j = blockIdx.x * 8 + wid;
    int lane = tid & 31;
    const __half2* wr2 = (const __half2*)(g_whh2 + (size_t)j * REC_D);
    const __half2* wz2 = (const __half2*)(g_whh2 + (size_t)(1024 + j) * REC_D);
    const __half2* wn2 = (const __half2*)(g_whh2 + (size_t)(2048 + j) * REC_D);
    __half2 wr[16], wz[16], wn[16];
#pragma unroll
    for (int q = 0; q < 16; q++) {
        wr[q] = wr2[lane + q * 32];
        wz[q] = wz2[lane + q * 32];
        wn[q] = wn2[lane + q * 32];
    }
    float bn = b_n[j];
    unsigned nb = gridDim.x;
    unsigned bc = 0;

    for (int k = GEMM_STEPS; k < STEPS; k++) {
        int count = g_counts[k];
        int base = g_offsets[k];
        if (count <= 0) continue;
        tail_prefetch(g_perm[base], sh[0], tid);
        cp_commit();
        for (int i = 0; i < count; i++) {
            if (i + 1 < count) tail_prefetch(g_perm[base + i + 1], sh[(i + 1) & 1], tid);
            cp_commit();
            if (i + 1 < count) cp_wait1(); else cp_wait0();
            __syncthreads();
            const __half2* hb = sh[i & 1];
            int t = g_perm[base + i];
            float aR = 0.0f, aZ = 0.0f, aN = 0.0f;
#pragma unroll
            for (int q = 0; q < 16; q++) {
                float2 hf = __half22float2(hb[lane + q * 32]);
                float2 rf = __half22float2(wr[q]);
                float2 zf = __half22float2(wz[q]);
                float2 nf = __half22float2(wn[q]);
                aR += rf.x * hf.x + rf.y * hf.y;
                aZ += zf.x * hf.x + zf.y * hf.y;
                aN += nf.x * hf.x + nf.y * hf.y;
            }
#pragma unroll
            for (int o = 16; o > 0; o >>= 1) {
                aR += __shfl_xor_sync(0xffffffffu, aR, o);
                aZ += __shfl_xor_sync(0xffffffffu, aZ, o);
                aN += __shfl_xor_sync(0xffffffffu, aN, o);
            }
            if (lane == 0) {
                float igr = ldh(&g_igates[(size_t)t * G3_D + j]);
                float igz = ldh(&g_igates[(size_t)t * G3_D + 1024 + j]);
                float ign = ldh(&g_igates[(size_t)t * G3_D + 2048 + j]);
                float hp = __ldcg(&g_states[(size_t)(t - 1) * REC_D + j]);
                float r = sigf(igr + aR);
                float z = sigf(igz + aZ);
                float n = tanhf(ign + r * (aN + bn));
                store_state(t, j, n + z * (hp - n));
            }
            __syncthreads();
        }
        bc++;
        __syncthreads();
        if (tid == 0) {
            __threadfence();
            atomicAdd(&g_bar, 1u);
            while (*((volatile unsigned*)&g_bar) < bc * nb) {}
        }
        __syncthreads();
    }
}

// safety net for age >= STEPS
__global__ void __launch_bounds__(1024)
cleanup_kernel(const float* __restrict__ w_hh, const float* __restrict__ b_n) {
    if (g_counts[STEPS] == 0) return;
    __shared__ int s_t;
    __shared__ int s_cur;
    __shared__ float sh[REC_D];
    int tid = threadIdx.x;
    if (tid == 0) s_cur = STEPS;
    __syncthreads();
    while (true) {
        if (tid == 0) {
            s_t = -1;
            for (int u = s_cur; u < T_LEN; ++u)
                if (g_age[u] >= STEPS) { s_t = u; s_cur = u + 1; break; }
        }
        __syncthreads();
        int t = s_t;
        if (t < 0) break;
        sh[tid] = g_states[(size_t)(t - 1) * REC_D + tid];
        __syncthreads();
        float aRv = 0, aZv = 0, aNv = 0;
        const float* wr = w_hh + (size_t)tid * REC_D;
        const float* wz = w_hh + (size_t)(1024 + tid) * REC_D;
        const float* wn = w_hh + (size_t)(2048 + tid) * REC_D;
        for (int kk = 0; kk < REC_D; kk++) {
            float h = sh[kk];
            aRv += wr[kk] * h; aZv += wz[kk] * h; aNv += wn[kk] * h;
        }
        float igr = ldh(&g_igates[(size_t)t * G3_D + tid]);
        float igz = ldh(&g_igates[(size_t)t * G3_D + 1024 + tid]);
        float ign = ldh(&g_igates[(size_t)t * G3_D + 2048 + tid]);
        float r = sigf(igr + aRv);
        float z = sigf(igz + aZv);
        float n = tanhf(ign + r * (aNv + b_n[tid]));
        float hp = sh[tid];
        store_state(t, tid, n + z * (hp - n));
        __syncthreads();
    }
}

__global__ void copy_state_kernel(float* __restrict__ out) {
    out[threadIdx.x] = g_states[(size_t)(T_LEN - 1) * REC_D + threadIdx.x];
}

// ---------------- host ----------------
extern "C" void kernel_launch(void* const* d_in, const int* in_sizes, int n_in,
                              void* d_out, int out_size) {
    const float* x     = (const float*)d_in[0];
    const float* state = (const float*)d_in[1];
    const void*  start = d_in[2];
    const float* pre_w = (const float*)d_in[4];
    const float* pre_b = (const float*)d_in[5];
    const float* w_ih  = (const float*)d_in[6];
    const float* w_hh  = (const float*)d_in[7];
    const float* b_ih  = (const float*)d_in[8];
    const float* b_n   = (const float*)d_in[9];
    const float* p1_w  = (const float*)d_in[10];
    const float* p1_b  = (const float*)d_in[11];
    const float* p2_w  = (const float*)d_in[12];
    const float* p2_b  = (const float*)d_in[13];
    const float* p3_w  = (const float*)d_in[14];
    const float* p3_b  = (const float*)d_in[15];
    float* out = (float*)d_out;

    f16 *x2, *prew2, *feat2, *wih2, *whh2, *p1w2, *p2w2, *p3w2, *states2, *y12;
    f16 *igates, *hg, *y2h;
    int* counts_dev;
    cudaGetSymbolAddress((void**)&igates, g_igates);
    cudaGetSymbolAddress((void**)&hg, g_hg);
    cudaGetSymbolAddress((void**)&y2h, g_y2h);
    cudaGetSymbolAddress((void**)&x2, g_x2);
    cudaGetSymbolAddress((void**)&prew2, g_prew2);
    cudaGetSymbolAddress((void**)&feat2, g_feat2);
    cudaGetSymbolAddress((void**)&wih2, g_wih2);
    cudaGetSymbolAddress((void**)&whh2, g_whh2);
    cudaGetSymbolAddress((void**)&p1w2, g_p1w2);
    cudaGetSymbolAddress((void**)&p2w2, g_p2w2);
    cudaGetSymbolAddress((void**)&p3w2, g_p3w2);
    cudaGetSymbolAddress((void**)&states2, g_states2);
    cudaGetSymbolAddress((void**)&y12, g_y12);
    cudaGetSymbolAddress((void**)&counts_dev, g_counts);

    cudaFuncSetAttribute(gemm_ca<1, 1, 0>, cudaFuncAttributeMaxDynamicSharedMemorySize, SMEM_GEMM);
    cudaFuncSetAttribute(gemm_ca<0, 1, 0>, cudaFuncAttributeMaxDynamicSharedMemorySize, SMEM_GEMM);
    cudaFuncSetAttribute(gemm_ca<0, 1, 1>, cudaFuncAttributeMaxDynamicSharedMemorySize, SMEM_GEMM);
    cudaFuncSetAttribute(gemm_sm, cudaFuncAttributeMaxDynamicSharedMemorySize, SMEM_SGEMM);
    cudaFuncSetAttribute(gemm_p3, cudaFuncAttributeMaxDynamicSharedMemorySize, SMEM_P3);

    // segment analysis (single launch)
    analyze_kernel<<<1, 1024>>>((const unsigned char*)start);

    // all conversions in one launch
    conv_all<<<1024, 256>>>(pre_w, prew2, (size_t)MLP_D * OBS_D,
                            w_ih, wih2, (size_t)G3_D * MLP_D,
                            w_hh, whh2, (size_t)G3_D * REC_D,
                            p1_w, p1w2, (size_t)MLP_D * REC_D,
                            p2_w, p2w2, (size_t)MLP_D * MLP_D,
                            x, x2, (size_t)T_LEN * OBS_D,
                            p3_w, p3w2);

    // feat = mish(x @ pre_w^T + pre_b)
    gemm_ca<1, 1, 0><<<dim3(MLP_D / 128, 128), 256, SMEM_GEMM>>>(
        x2, prew2, pre_b, nullptr, feat2, MLP_D, OBS_D, nullptr, T_LEN, 0);
    // igates = feat @ w_ih^T + b_ih (fp16 out)
    gemm_ca<0, 1, 0><<<dim3(G3_D / 128, 128), 256, SMEM_GEMM>>>(
        feat2, wih2, b_ih, nullptr, igates, G3_D, MLP_D, nullptr, T_LEN, 0);

    // segment-parallel GRU scan
    step0_kernel<<<2048, 256>>>(b_n);
    fixA_kernel<<<384, 256>>>(w_hh, state);
    fixB_kernel<<<1, 1024>>>(state, b_n);
    for (int k = 1; k < GEMM_STEPS; k++) {
        int est = T_LEN >> k;
        if (k == 1) {
            int gy = est / 128; if (gy < 1) gy = 1; if (gy > 64) gy = 64;
            gemm_ca<0, 1, 1><<<dim3(G3_D / 128, gy), 256, SMEM_GEMM>>>(
                states2, whh2, nullptr, nullptr, hg, G3_D, REC_D, counts_dev + k, 0, k);
        } else {
            int gy = est / 64; if (gy < 1) gy = 1; if (gy > 32) gy = 32;
            gemm_sm<<<dim3(G3_D / 128, gy), 256, SMEM_SGEMM>>>(
                states2, whh2, hg, G3_D, REC_D, counts_dev + k, k);
        }
        gru_gate<<<2048, 256>>>(b_n, k);
    }
    gru_tail_persistent<<<TAIL_BLOCKS, 256>>>(b_n);
    cleanup_kernel<<<1, 1024>>>(w_hh, b_n);

    // post MLP
    gemm_ca<1, 1, 0><<<dim3(MLP_D / 128, 128), 256, SMEM_GEMM>>>(
        states2, p1w2, p1_b, nullptr, y12, MLP_D, REC_D, nullptr, T_LEN, 0);
    gemm_ca<1, 1, 0><<<dim3(MLP_D / 128, 128), 256, SMEM_GEMM>>>(
        y12, p2w2, p2_b, nullptr, y2h, MLP_D, MLP_D, nullptr, T_LEN, 0);
    gemm_p3<<<T_LEN / 128, 256, SMEM_P3>>>(y2h, p3w2, p3_b, out);

    if (out_size >= T_LEN * ACT_D + REC_D)
        copy_state_kernel<<<1, 1024>>>(out + (size_t)T_LEN * ACT_D);
}